// round 2
// baseline (speedup 1.0000x reference)
#include <cuda_runtime.h>
#include <cuda_bf16.h>
#include <math.h>

#define B_ROWS 32768
#define N_CODE 8192
#define DIM    512
#define BD     (B_ROWS * DIM)

#define BM 128
#define BN 128
#define BK 16

// ---------------- device scratch (no allocations allowed) ----------------
__device__ float g_zz[B_ROWS];
__device__ float g_wn[N_CODE];
__device__ int   g_idx[B_ROWS];
__device__ int   g_counts[N_CODE];
__device__ float g_rowsse[B_ROWS];

// ---------------- row squared norms (one warp per row, deterministic) ----
__global__ void rownorm_kernel(const float* __restrict__ x, float* __restrict__ out, int rows) {
    int warp = (blockIdx.x * blockDim.x + threadIdx.x) >> 5;
    int lane = threadIdx.x & 31;
    if (warp >= rows) return;
    const float4* p = (const float4*)(x + (size_t)warp * DIM);
    float s = 0.0f;
    #pragma unroll
    for (int i = lane; i < DIM / 4; i += 32) {
        float4 v = p[i];
        s = fmaf(v.x, v.x, s);
        s = fmaf(v.y, v.y, s);
        s = fmaf(v.z, v.z, s);
        s = fmaf(v.w, v.w, s);
    }
    #pragma unroll
    for (int off = 16; off > 0; off >>= 1)
        s += __shfl_down_sync(0xFFFFFFFFu, s, off);
    if (lane == 0) out[warp] = s;
}

__global__ void zero_counts_kernel() {
    int i = blockIdx.x * blockDim.x + threadIdx.x;
    if (i < N_CODE) g_counts[i] = 0;
}

// ---------------- fused distance + argmin --------------------------------
// dist(r,c) = fl( fl(zz[r] + wn[c]) - 2*dot(z_r, w_c) )  (TEMPERATURE = 1)
// argmin with strict-< and ascending code order at every level -> matches
// jnp.argmin first-occurrence tie handling.
__global__ __launch_bounds__(256, 2)
void vq_argmin_kernel(const float* __restrict__ z, const float* __restrict__ W) {
    __shared__ float As[BK][BM];
    __shared__ float Bs[BK][BN];
    __shared__ float red_v[BM][17];
    __shared__ int   red_i[BM][17];
    __shared__ float best_v[BM];
    __shared__ int   best_i[BM];

    const int tid = threadIdx.x;
    const int tx = tid & 15;         // code sub-tile
    const int ty = tid >> 4;         // row sub-tile
    const int row0 = blockIdx.x * BM;

    if (tid < BM) {
        best_v[tid] = __int_as_float(0x7f800000);  // +inf
        best_i[tid] = 0;
    }

    // this thread's 8 row norms (fixed across chunks)
    float zzr[8];
    #pragma unroll
    for (int i = 0; i < 8; i++) zzr[i] = g_zz[row0 + ty * 8 + i];

    __syncthreads();

    for (int c0 = 0; c0 < N_CODE; c0 += BN) {
        float acc[8][8];
        #pragma unroll
        for (int i = 0; i < 8; i++)
            #pragma unroll
            for (int j = 0; j < 8; j++) acc[i][j] = 0.0f;

        for (int kk = 0; kk < DIM; kk += BK) {
            // load 128x16 z tile and 128x16 W tile, transposed into smem
            #pragma unroll
            for (int u = 0; u < 2; u++) {
                int l = tid * 2 + u;            // 0..511 float4s
                int r = l >> 2;
                int k = (l & 3) << 2;
                float4 v = *(const float4*)(&z[(size_t)(row0 + r) * DIM + kk + k]);
                As[k + 0][r] = v.x; As[k + 1][r] = v.y;
                As[k + 2][r] = v.z; As[k + 3][r] = v.w;
                float4 w = *(const float4*)(&W[(size_t)(c0 + r) * DIM + kk + k]);
                Bs[k + 0][r] = w.x; Bs[k + 1][r] = w.y;
                Bs[k + 2][r] = w.z; Bs[k + 3][r] = w.w;
            }
            __syncthreads();

            #pragma unroll
            for (int k = 0; k < BK; k++) {
                float4 a0 = *(const float4*)&As[k][ty * 8];
                float4 a1 = *(const float4*)&As[k][ty * 8 + 4];
                float4 b0 = *(const float4*)&Bs[k][tx * 8];
                float4 b1 = *(const float4*)&Bs[k][tx * 8 + 4];
                float a[8] = {a0.x, a0.y, a0.z, a0.w, a1.x, a1.y, a1.z, a1.w};
                float b[8] = {b0.x, b0.y, b0.z, b0.w, b1.x, b1.y, b1.z, b1.w};
                #pragma unroll
                for (int i = 0; i < 8; i++)
                    #pragma unroll
                    for (int j = 0; j < 8; j++)
                        acc[i][j] = fmaf(a[i], b[j], acc[i][j]);
            }
            __syncthreads();
        }

        // per-thread argmin over its 8 codes for each of its 8 rows
        float wnj[8];
        #pragma unroll
        for (int j = 0; j < 8; j++) wnj[j] = g_wn[c0 + tx * 8 + j];

        #pragma unroll
        for (int i = 0; i < 8; i++) {
            float bv = __int_as_float(0x7f800000);
            int   bj = 0;
            #pragma unroll
            for (int j = 0; j < 8; j++) {
                float t = zzr[i] + wnj[j];            // fl(zz + wn)
                float d = t - 2.0f * acc[i][j];       // fl(t - 2*dot)
                if (d < bv) { bv = d; bj = j; }       // strict <, ascending j
            }
            red_v[ty * 8 + i][tx] = bv;
            red_i[ty * 8 + i][tx] = c0 + tx * 8 + bj;
        }
        __syncthreads();

        // 128 threads: reduce 16 candidates per row in ascending code order
        if (tid < BM) {
            float bv = best_v[tid];
            int   bi = best_i[tid];
            #pragma unroll
            for (int t = 0; t < 16; t++) {
                float v = red_v[tid][t];
                if (v < bv) { bv = v; bi = red_i[tid][t]; }
            }
            best_v[tid] = bv;
            best_i[tid] = bi;
        }
        __syncthreads();
    }

    if (tid < BM) g_idx[row0 + tid] = best_i[tid];
}

// ---------------- histogram ----------------------------------------------
__global__ void hist_kernel() {
    int i = blockIdx.x * blockDim.x + threadIdx.x;
    if (i < B_ROWS) atomicAdd(&g_counts[g_idx[i]], 1);
}

// ---------------- gather + per-row SSE + index write ----------------------
__global__ void gather_sse_kernel(const float* __restrict__ z,
                                  const float* __restrict__ W,
                                  float* __restrict__ out) {
    __shared__ float sh[128];
    int row = blockIdx.x;
    int t = threadIdx.x;                 // 128 threads, one float4 each
    int code = g_idx[row];

    const float4* zp = (const float4*)(z + (size_t)row * DIM);
    const float4* wp = (const float4*)(W + (size_t)code * DIM);
    float4 a = zp[t];
    float4 b = wp[t];
    ((float4*)out)[(size_t)row * (DIM / 4) + t] = b;   // quantized_st == W[idx]

    float dx = a.x - b.x, dy = a.y - b.y, dz = a.z - b.z, dw = a.w - b.w;
    sh[t] = dx * dx + dy * dy + dz * dz + dw * dw;
    __syncthreads();
    #pragma unroll
    for (int off = 64; off > 0; off >>= 1) {
        if (t < off) sh[t] += sh[t + off];
        __syncthreads();
    }
    if (t == 0) {
        g_rowsse[row] = sh[0];
        out[BD + 1 + row] = (float)code;               // indices as float
    }
}

// ---------------- final deterministic reduction + loss --------------------
__global__ void finalize_kernel(float* __restrict__ out) {
    __shared__ float sh[1024];
    int t = threadIdx.x;

    float s = 0.0f;
    for (int i = t; i < B_ROWS; i += 1024) s += g_rowsse[i];
    sh[t] = s;
    __syncthreads();
    #pragma unroll
    for (int off = 512; off > 0; off >>= 1) {
        if (t < off) sh[t] += sh[t + off];
        __syncthreads();
    }
    float sse = sh[0];
    __syncthreads();

    float e = 0.0f;
    for (int i = t; i < N_CODE; i += 1024) {
        float c = (float)g_counts[i];
        float p = c * (1.0f / (float)B_ROWS);
        e -= p * logf(p + 1e-10f);
    }
    sh[t] = e;
    __syncthreads();
    #pragma unroll
    for (int off = 512; off > 0; off >>= 1) {
        if (t < off) sh[t] += sh[t + off];
        __syncthreads();
    }
    if (t == 0) {
        float ent = sh[0];
        float mse = sse / (float)BD;
        float entropy_loss = 1.0f - ent / logf((float)N_CODE);
        out[BD] = 1.25f * mse + 0.1f * entropy_loss;
    }
}

// ---------------- launch ---------------------------------------------------
extern "C" void kernel_launch(void* const* d_in, const int* in_sizes, int n_in,
                              void* d_out, int out_size) {
    const float* z = (const float*)d_in[0];
    const float* W = (const float*)d_in[1];
    float* out = (float*)d_out;

    float* zz; cudaGetSymbolAddress((void**)&zz, g_zz);
    float* wn; cudaGetSymbolAddress((void**)&wn, g_wn);

    // row norms: one warp per row, 256 threads/block = 8 warps
    rownorm_kernel<<<B_ROWS / 8, 256>>>(z, zz, B_ROWS);
    rownorm_kernel<<<N_CODE / 8, 256>>>(W, wn, N_CODE);
    zero_counts_kernel<<<N_CODE / 256, 256>>>();

    vq_argmin_kernel<<<B_ROWS / BM, 256>>>(z, W);

    hist_kernel<<<B_ROWS / 256, 256>>>();
    gather_sse_kernel<<<B_ROWS, 128>>>(z, W, out);
    finalize_kernel<<<1, 1024>>>(out);
}

// round 4
// speedup vs baseline: 2.4800x; 2.4800x over previous
#include <cuda_runtime.h>
#include <cuda_bf16.h>
#include <cstdint>
#include <math.h>

#define B_ROWS 32768
#define N_CODE 8192
#define DIM    512
#define KP     1536            // packed K: A=[hi|hi|lo], B=[hi|lo|hi]
#define BD     (B_ROWS * DIM)

#define NMT 2                  // M-tiles per CTA
#define NNT 64                 // N-tiles (8192 / 128)
#define NKC 24                 // K-chunks of 64 per N-tile (1536/64)
#define GTOT (NMT * NNT * NKC) // 3072 flat pipeline iterations
#define STAGES 3
#define STAGE_BYTES 32768      // A 16K + B 16K (128 rows x 128B each)
#define SMEM_EPI (STAGES * STAGE_BYTES)
#define SMEM_TOTAL (SMEM_EPI + 128*4*6)   // best_v/i + cand_v/i[2]

// ---------------- device scratch ----------------
__device__ __nv_bfloat16 g_Az[(size_t)B_ROWS * KP];   // ~100 MB
__device__ __nv_bfloat16 g_Bw[(size_t)N_CODE * KP];   // ~25 MB
__device__ float g_zz[B_ROWS];
__device__ float g_wn[N_CODE];
__device__ int   g_idx[B_ROWS];
__device__ int   g_counts[N_CODE];
__device__ float g_rowsse[B_ROWS];

// ---------------- helpers ----------------
__device__ __forceinline__ uint32_t smem_u32(const void* p) {
    uint32_t a;
    asm("{ .reg .u64 t; cvta.to.shared.u64 t, %1; cvt.u32.u64 %0, t; }" : "=r"(a) : "l"(p));
    return a;
}
__device__ __forceinline__ void cp16(uint32_t dst, const void* src) {
    asm volatile("cp.async.cg.shared.global [%0], [%1], 16;" :: "r"(dst), "l"(src));
}
#define CP_COMMIT() asm volatile("cp.async.commit_group;" ::: "memory")
#define CP_WAIT1()  asm volatile("cp.async.wait_group 1;" ::: "memory")

#define LDM_X4(r0, r1, r2, r3, a)                                              \
    asm volatile("ldmatrix.sync.aligned.m8n8.x4.shared.b16 {%0,%1,%2,%3}, [%4];" \
        : "=r"(r0), "=r"(r1), "=r"(r2), "=r"(r3) : "r"(a))

#define MMA_BF16(d, a, b)                                                      \
    asm volatile("mma.sync.aligned.m16n8k16.row.col.f32.bf16.bf16.f32 "        \
        "{%0,%1,%2,%3},{%4,%5,%6,%7},{%8,%9},{%0,%1,%2,%3};"                   \
        : "+f"((d)[0]), "+f"((d)[1]), "+f"((d)[2]), "+f"((d)[3])               \
        : "r"((a)[0]), "r"((a)[1]), "r"((a)[2]), "r"((a)[3]),                  \
          "r"((b)[0]), "r"((b)[1]))

// ---------------- pack: fp32 -> bf16 hi/lo split ----------------
__global__ void pack_z_kernel(const float* __restrict__ z) {
    size_t i = (size_t)blockIdx.x * blockDim.x + threadIdx.x;
    if (i >= (size_t)B_ROWS * DIM) return;
    size_t r = i >> 9, k = i & 511;
    float x = z[i];
    __nv_bfloat16 hi = __float2bfloat16(x);
    __nv_bfloat16 lo = __float2bfloat16(x - __bfloat162float(hi));
    size_t b = r * KP;
    g_Az[b + k] = hi;
    g_Az[b + 512 + k] = hi;
    g_Az[b + 1024 + k] = lo;
}
__global__ void pack_w_kernel(const float* __restrict__ W) {
    size_t i = (size_t)blockIdx.x * blockDim.x + threadIdx.x;
    if (i >= (size_t)N_CODE * DIM) return;
    size_t r = i >> 9, k = i & 511;
    float x = W[i];
    __nv_bfloat16 hi = __float2bfloat16(x);
    __nv_bfloat16 lo = __float2bfloat16(x - __bfloat162float(hi));
    size_t b = r * KP;
    g_Bw[b + k] = hi;
    g_Bw[b + 512 + k] = lo;
    g_Bw[b + 1024 + k] = hi;
}

// ---------------- row norms ----------------
__global__ void rownorm_kernel(const float* __restrict__ x, float* __restrict__ out, int rows) {
    int warp = (blockIdx.x * blockDim.x + threadIdx.x) >> 5;
    int lane = threadIdx.x & 31;
    if (warp >= rows) return;
    const float4* p = (const float4*)(x + (size_t)warp * DIM);
    float s = 0.0f;
    #pragma unroll
    for (int i = lane; i < DIM / 4; i += 32) {
        float4 v = p[i];
        s = fmaf(v.x, v.x, s); s = fmaf(v.y, v.y, s);
        s = fmaf(v.z, v.z, s); s = fmaf(v.w, v.w, s);
    }
    #pragma unroll
    for (int off = 16; off > 0; off >>= 1) s += __shfl_down_sync(0xFFFFFFFFu, s, off);
    if (lane == 0) out[warp] = s;
}

__global__ void zero_counts_kernel() {
    int i = blockIdx.x * blockDim.x + threadIdx.x;
    if (i < N_CODE) g_counts[i] = 0;
}

// ---------------- main HMMA GEMM + fused argmin ----------------
// grid=128 CTAs; each: 2 M-tiles x 64 N-tiles x (K=1536). 256 threads,
// 8 warps arranged 4(M) x 2(N); warp tile 32x64.
__global__ __launch_bounds__(256, 1) void vq_mma_kernel() {
    extern __shared__ char smem[];
    const uint32_t sb = smem_u32(smem);
    float* best_v = (float*)(smem + SMEM_EPI);
    int*   best_i = (int*)  (smem + SMEM_EPI + 512);
    float* cand_v = (float*)(smem + SMEM_EPI + 1024);   // [2][128]
    int*   cand_i = (int*)  (smem + SMEM_EPI + 2048);   // [2][128]

    const int tid   = threadIdx.x;
    const int lane  = tid & 31;
    const int wid   = tid >> 5;
    const int warpM = wid & 3;
    const int warpN = wid >> 2;
    const int q     = lane & 3;

    if (tid < 128) { best_v[tid] = __int_as_float(0x7f800000); best_i[tid] = 0; }

    float acc[2][8][4];
    #pragma unroll
    for (int mi = 0; mi < 2; mi++)
        #pragma unroll
        for (int n8 = 0; n8 < 8; n8++)
            #pragma unroll
            for (int r = 0; r < 4; r++) acc[mi][n8][r] = 0.0f;

    // loader lambda-ish: stage s gets iteration g's tiles
    auto load_tiles = [&](int g) {
        const int mt = blockIdx.x * NMT + g / (NNT * NKC);
        const int nt = (g / NKC) % NNT;
        const int kc = g % NKC;
        const uint32_t stage = sb + (uint32_t)(g % STAGES) * STAGE_BYTES;
        const __nv_bfloat16* Asrc = g_Az + (size_t)(mt * 128) * KP + kc * 64;
        const __nv_bfloat16* Bsrc = g_Bw + (size_t)(nt * 128) * KP + kc * 64;
        #pragma unroll
        for (int i = 0; i < 4; i++) {
            int lin = tid + 256 * i;           // 0..1023
            int row = lin >> 3, c = lin & 7;
            uint32_t off = (uint32_t)row * 128u + (uint32_t)((c ^ (row & 7)) << 4);
            cp16(stage + off,           Asrc + (size_t)row * KP + c * 8);
            cp16(stage + 16384u + off,  Bsrc + (size_t)row * KP + c * 8);
        }
        CP_COMMIT();
    };

    load_tiles(0);
    load_tiles(1);

    for (int g = 0; g < GTOT; g++) {
        CP_WAIT1();
        __syncthreads();
        if (g + 2 < GTOT) load_tiles(g + 2);

        const uint32_t Abase = sb + (uint32_t)(g % STAGES) * STAGE_BYTES;
        const uint32_t Bbase = Abase + 16384u;

        #pragma unroll
        for (int s = 0; s < 4; s++) {
            uint32_t afr[2][4];
            #pragma unroll
            for (int mi = 0; mi < 2; mi++) {
                int row = warpM * 32 + mi * 16 + (lane & 15);
                int c = 2 * s + (lane >> 4);
                uint32_t addr = Abase + (uint32_t)row * 128u + (uint32_t)((c ^ (row & 7)) << 4);
                LDM_X4(afr[mi][0], afr[mi][1], afr[mi][2], afr[mi][3], addr);
            }
            uint32_t bfr[8][2];
            #pragma unroll
            for (int ni2 = 0; ni2 < 4; ni2++) {
                int row = warpN * 64 + ni2 * 16 + ((lane >> 4) << 3) + (lane & 7);
                int c = 2 * s + ((lane >> 3) & 1);
                uint32_t addr = Bbase + (uint32_t)row * 128u + (uint32_t)((c ^ (row & 7)) << 4);
                LDM_X4(bfr[2 * ni2][0], bfr[2 * ni2][1],
                       bfr[2 * ni2 + 1][0], bfr[2 * ni2 + 1][1], addr);
            }
            #pragma unroll
            for (int mi = 0; mi < 2; mi++)
                #pragma unroll
                for (int n8 = 0; n8 < 8; n8++)
                    MMA_BF16(acc[mi][n8], afr[mi], bfr[n8]);
        }

        if ((g % NKC) == NKC - 1) {
            // ---------- epilogue for this (mt, nt) tile ----------
            const int mt = blockIdx.x * NMT + g / (NNT * NKC);
            const int nt = (g / NKC) % NNT;
            const int cb = nt * 128 + warpN * 64 + 2 * q;

            float wnv[16];
            #pragma unroll
            for (int n8 = 0; n8 < 8; n8++) {
                wnv[n8 * 2]     = __ldg(&g_wn[cb + n8 * 8]);
                wnv[n8 * 2 + 1] = __ldg(&g_wn[cb + n8 * 8 + 1]);
            }

            #pragma unroll
            for (int mi = 0; mi < 2; mi++) {
                #pragma unroll
                for (int h = 0; h < 2; h++) {
                    int lrow = warpM * 32 + mi * 16 + (lane >> 2) + 8 * h;
                    float zzv = __ldg(&g_zz[mt * 128 + lrow]);
                    float bv = __int_as_float(0x7f800000);
                    int bc = 0;
                    #pragma unroll
                    for (int n8 = 0; n8 < 8; n8++) {
                        #pragma unroll
                        for (int j = 0; j < 2; j++) {
                            float v = acc[mi][n8][h * 2 + j];
                            float d = (zzv + wnv[n8 * 2 + j]) - 2.0f * v;
                            int c = cb + n8 * 8 + j;
                            if (d < bv || (d == bv && c < bc)) { bv = d; bc = c; }
                        }
                    }
                    #pragma unroll
                    for (int off = 1; off <= 2; off <<= 1) {
                        float ov = __shfl_xor_sync(0xFFFFFFFFu, bv, off);
                        int   oc = __shfl_xor_sync(0xFFFFFFFFu, bc, off);
                        if (ov < bv || (ov == bv && oc < bc)) { bv = ov; bc = oc; }
                    }
                    if (q == 0) {
                        cand_v[warpN * 128 + lrow] = bv;
                        cand_i[warpN * 128 + lrow] = bc;
                    }
                }
            }
            __syncthreads();
            if (tid < 128) {
                float bv = best_v[tid]; int bc = best_i[tid];
                float v0 = cand_v[tid];       int c0 = cand_i[tid];
                float v1 = cand_v[128 + tid]; int c1 = cand_i[128 + tid];
                if (v0 < bv || (v0 == bv && c0 < bc)) { bv = v0; bc = c0; }
                if (v1 < bv || (v1 == bv && c1 < bc)) { bv = v1; bc = c1; }
                if (nt == NNT - 1) {
                    g_idx[mt * 128 + tid] = bc;
                    best_v[tid] = __int_as_float(0x7f800000); best_i[tid] = 0;
                } else {
                    best_v[tid] = bv; best_i[tid] = bc;
                }
            }
            #pragma unroll
            for (int mi = 0; mi < 2; mi++)
                #pragma unroll
                for (int n8 = 0; n8 < 8; n8++)
                    #pragma unroll
                    for (int r = 0; r < 4; r++) acc[mi][n8][r] = 0.0f;
        }
    }
}

// ---------------- histogram ----------------
__global__ void hist_kernel() {
    int i = blockIdx.x * blockDim.x + threadIdx.x;
    if (i < B_ROWS) atomicAdd(&g_counts[g_idx[i]], 1);
}

// ---------------- gather + per-row SSE + index write ----------------
__global__ void gather_sse_kernel(const float* __restrict__ z,
                                  const float* __restrict__ W,
                                  float* __restrict__ out) {
    __shared__ float sh[128];
    int row = blockIdx.x;
    int t = threadIdx.x;
    int code = g_idx[row];
    const float4* zp = (const float4*)(z + (size_t)row * DIM);
    const float4* wp = (const float4*)(W + (size_t)code * DIM);
    float4 a = zp[t];
    float4 b = wp[t];
    ((float4*)out)[(size_t)row * (DIM / 4) + t] = b;
    float dx = a.x - b.x, dy = a.y - b.y, dz = a.z - b.z, dw = a.w - b.w;
    sh[t] = dx * dx + dy * dy + dz * dz + dw * dw;
    __syncthreads();
    #pragma unroll
    for (int off = 64; off > 0; off >>= 1) {
        if (t < off) sh[t] += sh[t + off];
        __syncthreads();
    }
    if (t == 0) {
        g_rowsse[row] = sh[0];
        out[BD + 1 + row] = (float)code;
    }
}

// ---------------- final loss ----------------
__global__ void finalize_kernel(float* __restrict__ out) {
    __shared__ float sh[1024];
    int t = threadIdx.x;
    float s = 0.0f;
    for (int i = t; i < B_ROWS; i += 1024) s += g_rowsse[i];
    sh[t] = s;
    __syncthreads();
    #pragma unroll
    for (int off = 512; off > 0; off >>= 1) {
        if (t < off) sh[t] += sh[t + off];
        __syncthreads();
    }
    float sse = sh[0];
    __syncthreads();
    float e = 0.0f;
    for (int i = t; i < N_CODE; i += 1024) {
        float c = (float)g_counts[i];
        float p = c * (1.0f / (float)B_ROWS);
        e -= p * logf(p + 1e-10f);
    }
    sh[t] = e;
    __syncthreads();
    #pragma unroll
    for (int off = 512; off > 0; off >>= 1) {
        if (t < off) sh[t] += sh[t + off];
        __syncthreads();
    }
    if (t == 0) {
        float mse = sse / (float)BD;
        float entropy_loss = 1.0f - sh[0] / logf((float)N_CODE);
        out[BD] = 1.25f * mse + 0.1f * entropy_loss;
    }
}

// ---------------- launch ----------------
extern "C" void kernel_launch(void* const* d_in, const int* in_sizes, int n_in,
                              void* d_out, int out_size) {
    const float* z = (const float*)d_in[0];
    const float* W = (const float*)d_in[1];
    float* out = (float*)d_out;

    float* zz; cudaGetSymbolAddress((void**)&zz, g_zz);
    float* wn; cudaGetSymbolAddress((void**)&wn, g_wn);

    cudaFuncSetAttribute(vq_mma_kernel,
                         cudaFuncAttributeMaxDynamicSharedMemorySize, SMEM_TOTAL);

    pack_z_kernel<<<(B_ROWS * DIM + 255) / 256, 256>>>(z);
    pack_w_kernel<<<(N_CODE * DIM + 255) / 256, 256>>>(W);
    rownorm_kernel<<<B_ROWS / 8, 256>>>(z, zz, B_ROWS);
    rownorm_kernel<<<N_CODE / 8, 256>>>(W, wn, N_CODE);
    zero_counts_kernel<<<N_CODE / 256, 256>>>();

    vq_mma_kernel<<<B_ROWS / (128 * NMT), 256, SMEM_TOTAL>>>();

    hist_kernel<<<B_ROWS / 256, 256>>>();
    gather_sse_kernel<<<B_ROWS, 128>>>(z, W, out);
    finalize_kernel<<<1, 1024>>>(out);
}

// round 5
// speedup vs baseline: 3.4584x; 1.3945x over previous
#include <cuda_runtime.h>
#include <cuda_bf16.h>
#include <cstdint>
#include <math.h>

#define B_ROWS 32768
#define N_CODE 8192
#define DIM    512
#define KP     1536            // packed K: A=[hi|hi|lo], B=[hi|lo|hi]
#define BD     (B_ROWS * DIM)

#define UNITS  8192            // 256 mt x 32 nt
#define NKC    24              // K-chunks of 64 per unit (1536/64)
#define STAGES 3
#define STAGE_BYTES 49152      // A 16K (128x128B) + B 32K (256x128B)
#define SMEM_EPI (STAGES * STAGE_BYTES)
#define SMEM_TOTAL (SMEM_EPI + 4096)   // cand_v[4][128] + cand_i[4][128]

// ---------------- device scratch ----------------
__device__ __nv_bfloat16 g_Az[(size_t)B_ROWS * KP];   // ~100 MB
__device__ __nv_bfloat16 g_Bw[(size_t)N_CODE * KP];   // ~25 MB
__device__ float g_zz[B_ROWS];
__device__ float g_wn[N_CODE];
__device__ unsigned long long g_best[B_ROWS];
__device__ int   g_counts[N_CODE];
__device__ float g_rowsse[B_ROWS];

// ---------------- helpers ----------------
__device__ __forceinline__ uint32_t smem_u32(const void* p) {
    uint32_t a;
    asm("{ .reg .u64 t; cvta.to.shared.u64 t, %1; cvt.u32.u64 %0, t; }" : "=r"(a) : "l"(p));
    return a;
}
__device__ __forceinline__ void cp16(uint32_t dst, const void* src) {
    asm volatile("cp.async.cg.shared.global [%0], [%1], 16;" :: "r"(dst), "l"(src));
}
#define CP_COMMIT() asm volatile("cp.async.commit_group;" ::: "memory")
#define CP_WAIT1()  asm volatile("cp.async.wait_group 1;" ::: "memory")

#define LDM_X4(r0, r1, r2, r3, a)                                              \
    asm volatile("ldmatrix.sync.aligned.m8n8.x4.shared.b16 {%0,%1,%2,%3}, [%4];" \
        : "=r"(r0), "=r"(r1), "=r"(r2), "=r"(r3) : "r"(a))

#define MMA_BF16(d, a, b)                                                      \
    asm volatile("mma.sync.aligned.m16n8k16.row.col.f32.bf16.bf16.f32 "        \
        "{%0,%1,%2,%3},{%4,%5,%6,%7},{%8,%9},{%0,%1,%2,%3};"                   \
        : "+f"((d)[0]), "+f"((d)[1]), "+f"((d)[2]), "+f"((d)[3])               \
        : "r"((a)[0]), "r"((a)[1]), "r"((a)[2]), "r"((a)[3]),                  \
          "r"((b)[0]), "r"((b)[1]))

// distances are positive but use the full order-preserving transform anyway
__device__ __forceinline__ uint32_t f2ord(float f) {
    uint32_t u = __float_as_uint(f);
    return (u & 0x80000000u) ? ~u : (u | 0x80000000u);
}

// ---------------- pack: fp32 -> bf16 hi/lo split ----------------
__global__ void pack_z_kernel(const float* __restrict__ z) {
    size_t i = (size_t)blockIdx.x * blockDim.x + threadIdx.x;
    if (i >= (size_t)B_ROWS * DIM) return;
    size_t r = i >> 9, k = i & 511;
    float x = z[i];
    __nv_bfloat16 hi = __float2bfloat16(x);
    __nv_bfloat16 lo = __float2bfloat16(x - __bfloat162float(hi));
    size_t b = r * KP;
    g_Az[b + k] = hi;
    g_Az[b + 512 + k] = hi;
    g_Az[b + 1024 + k] = lo;
}
__global__ void pack_w_kernel(const float* __restrict__ W) {
    size_t i = (size_t)blockIdx.x * blockDim.x + threadIdx.x;
    if (i >= (size_t)N_CODE * DIM) return;
    size_t r = i >> 9, k = i & 511;
    float x = W[i];
    __nv_bfloat16 hi = __float2bfloat16(x);
    __nv_bfloat16 lo = __float2bfloat16(x - __bfloat162float(hi));
    size_t b = r * KP;
    g_Bw[b + k] = hi;
    g_Bw[b + 512 + k] = lo;
    g_Bw[b + 1024 + k] = hi;
}

// ---------------- row norms ----------------
__global__ void rownorm_kernel(const float* __restrict__ x, float* __restrict__ out, int rows) {
    int warp = (blockIdx.x * blockDim.x + threadIdx.x) >> 5;
    int lane = threadIdx.x & 31;
    if (warp >= rows) return;
    const float4* p = (const float4*)(x + (size_t)warp * DIM);
    float s = 0.0f;
    #pragma unroll
    for (int i = lane; i < DIM / 4; i += 32) {
        float4 v = p[i];
        s = fmaf(v.x, v.x, s); s = fmaf(v.y, v.y, s);
        s = fmaf(v.z, v.z, s); s = fmaf(v.w, v.w, s);
    }
    #pragma unroll
    for (int off = 16; off > 0; off >>= 1) s += __shfl_down_sync(0xFFFFFFFFu, s, off);
    if (lane == 0) out[warp] = s;
}

__global__ void init_kernel() {
    int i = blockIdx.x * blockDim.x + threadIdx.x;
    if (i < N_CODE) g_counts[i] = 0;
    if (i < B_ROWS) g_best[i] = 0xFFFFFFFFFFFFFFFFull;
}

// ---------------- main HMMA GEMM + fused argmin ----------------
// persistent grid = #SMs; units = 256 mt x 32 nt, unit tile 128x256, K=1536.
// 8 warps: warpM = wid&1 (64 rows), warpN = wid>>1 (64 cols). Warp tile 64x64.
__global__ __launch_bounds__(256, 1) void vq_mma_kernel(int grid) {
    extern __shared__ char smem[];
    const uint32_t sb = smem_u32(smem);
    float* cand_v = (float*)(smem + SMEM_EPI);          // [4][128]
    int*   cand_i = (int*)  (smem + SMEM_EPI + 2048);   // [4][128]

    const int tid   = threadIdx.x;
    const int lane  = tid & 31;
    const int wid   = tid >> 5;
    const int warpM = wid & 1;
    const int warpN = wid >> 1;
    const int q     = lane & 3;
    const int bid   = blockIdx.x;

    const int nu = (UNITS - 1 - bid) / grid + 1;
    const int GT = nu * NKC;

    float acc[4][8][4];
    #pragma unroll
    for (int mi = 0; mi < 4; mi++)
        #pragma unroll
        for (int n8 = 0; n8 < 8; n8++)
            #pragma unroll
            for (int r = 0; r < 4; r++) acc[mi][n8][r] = 0.0f;

    auto load_tiles = [&](int g) {
        const int ui = g / NKC;
        const int kc = g - ui * NKC;
        const int w  = bid + ui * grid;
        const int mt = w >> 5;
        const int nt = w & 31;
        const uint32_t stage = sb + (uint32_t)(g % STAGES) * STAGE_BYTES;
        const __nv_bfloat16* Asrc = g_Az + (size_t)(mt * 128) * KP + kc * 64;
        const __nv_bfloat16* Bsrc = g_Bw + (size_t)(nt * 256) * KP + kc * 64;
        #pragma unroll
        for (int i = 0; i < 4; i++) {
            int lin = tid + 256 * i;           // 0..1023
            int row = lin >> 3, c = lin & 7;
            uint32_t off = (uint32_t)row * 128u + (uint32_t)((c ^ (row & 7)) << 4);
            cp16(stage + off, Asrc + (size_t)row * KP + c * 8);
        }
        #pragma unroll
        for (int i = 0; i < 8; i++) {
            int lin = tid + 256 * i;           // 0..2047
            int row = lin >> 3, c = lin & 7;
            uint32_t off = (uint32_t)row * 128u + (uint32_t)((c ^ (row & 7)) << 4);
            cp16(stage + 16384u + off, Bsrc + (size_t)row * KP + c * 8);
        }
        CP_COMMIT();
    };

    load_tiles(0);
    if (GT > 1) load_tiles(1);

    for (int g = 0; g < GT; g++) {
        CP_WAIT1();
        __syncthreads();
        if (g + 2 < GT) load_tiles(g + 2);

        const uint32_t Abase = sb + (uint32_t)(g % STAGES) * STAGE_BYTES;
        const uint32_t Bbase = Abase + 16384u;

        #pragma unroll
        for (int s = 0; s < 4; s++) {
            uint32_t afr[4][4];
            #pragma unroll
            for (int mi = 0; mi < 4; mi++) {
                int row = warpM * 64 + mi * 16 + (lane & 15);
                int c = 2 * s + (lane >> 4);
                uint32_t addr = Abase + (uint32_t)row * 128u + (uint32_t)((c ^ (row & 7)) << 4);
                LDM_X4(afr[mi][0], afr[mi][1], afr[mi][2], afr[mi][3], addr);
            }
            uint32_t bfr[8][2];
            #pragma unroll
            for (int ni2 = 0; ni2 < 4; ni2++) {
                int row = warpN * 64 + ni2 * 16 + ((lane >> 4) << 3) + (lane & 7);
                int c = 2 * s + ((lane >> 3) & 1);
                uint32_t addr = Bbase + (uint32_t)row * 128u + (uint32_t)((c ^ (row & 7)) << 4);
                LDM_X4(bfr[2 * ni2][0], bfr[2 * ni2][1],
                       bfr[2 * ni2 + 1][0], bfr[2 * ni2 + 1][1], addr);
            }
            #pragma unroll
            for (int mi = 0; mi < 4; mi++)
                #pragma unroll
                for (int n8 = 0; n8 < 8; n8++)
                    MMA_BF16(acc[mi][n8], afr[mi], bfr[n8]);
        }

        const int ui = g / NKC;
        if (g - ui * NKC == NKC - 1) {
            // ---------- epilogue for unit (mt, nt) ----------
            const int w  = bid + ui * grid;
            const int mt = w >> 5;
            const int nt = w & 31;
            const int cb = nt * 256 + warpN * 64 + 2 * q;

            float wnv[16];
            #pragma unroll
            for (int n8 = 0; n8 < 8; n8++) {
                wnv[n8 * 2]     = __ldg(&g_wn[cb + n8 * 8]);
                wnv[n8 * 2 + 1] = __ldg(&g_wn[cb + n8 * 8 + 1]);
            }

            #pragma unroll
            for (int mi = 0; mi < 4; mi++) {
                #pragma unroll
                for (int h = 0; h < 2; h++) {
                    int lrow = warpM * 64 + mi * 16 + (lane >> 2) + 8 * h;
                    float zzv = __ldg(&g_zz[mt * 128 + lrow]);
                    float bv = __int_as_float(0x7f800000);
                    int bc = 0;
                    #pragma unroll
                    for (int n8 = 0; n8 < 8; n8++) {
                        #pragma unroll
                        for (int j = 0; j < 2; j++) {
                            float v = acc[mi][n8][h * 2 + j];
                            float d = (zzv + wnv[n8 * 2 + j]) - 2.0f * v;
                            int c = cb + n8 * 8 + j;
                            if (d < bv || (d == bv && c < bc)) { bv = d; bc = c; }
                        }
                    }
                    #pragma unroll
                    for (int off = 1; off <= 2; off <<= 1) {
                        float ov = __shfl_xor_sync(0xFFFFFFFFu, bv, off);
                        int   oc = __shfl_xor_sync(0xFFFFFFFFu, bc, off);
                        if (ov < bv || (ov == bv && oc < bc)) { bv = ov; bc = oc; }
                    }
                    if (q == 0) {
                        cand_v[warpN * 128 + lrow] = bv;
                        cand_i[warpN * 128 + lrow] = bc;
                    }
                }
            }
            __syncthreads();
            if (tid < 128) {
                float bv = cand_v[tid]; int bc = cand_i[tid];
                #pragma unroll
                for (int wn = 1; wn < 4; wn++) {
                    float v = cand_v[wn * 128 + tid];
                    int   c = cand_i[wn * 128 + tid];
                    if (v < bv || (v == bv && c < bc)) { bv = v; bc = c; }
                }
                unsigned long long key =
                    ((unsigned long long)f2ord(bv) << 32) | (unsigned)bc;
                atomicMin(&g_best[mt * 128 + tid], key);
            }
            #pragma unroll
            for (int mi = 0; mi < 4; mi++)
                #pragma unroll
                for (int n8 = 0; n8 < 8; n8++)
                    #pragma unroll
                    for (int r = 0; r < 4; r++) acc[mi][n8][r] = 0.0f;
        }
    }
}

// ---------------- histogram ----------------
__global__ void hist_kernel() {
    int i = blockIdx.x * blockDim.x + threadIdx.x;
    if (i < B_ROWS) atomicAdd(&g_counts[(unsigned)(g_best[i] & 0xFFFFFFFFull)], 1);
}

// ---------------- gather + per-row SSE + index write ----------------
__global__ void gather_sse_kernel(const float* __restrict__ z,
                                  const float* __restrict__ W,
                                  float* __restrict__ out) {
    __shared__ float sh[128];
    int row = blockIdx.x;
    int t = threadIdx.x;
    int code = (int)(unsigned)(g_best[row] & 0xFFFFFFFFull);
    const float4* zp = (const float4*)(z + (size_t)row * DIM);
    const float4* wp = (const float4*)(W + (size_t)code * DIM);
    float4 a = zp[t];
    float4 b = wp[t];
    ((float4*)out)[(size_t)row * (DIM / 4) + t] = b;
    float dx = a.x - b.x, dy = a.y - b.y, dz = a.z - b.z, dw = a.w - b.w;
    sh[t] = dx * dx + dy * dy + dz * dz + dw * dw;
    __syncthreads();
    #pragma unroll
    for (int off = 64; off > 0; off >>= 1) {
        if (t < off) sh[t] += sh[t + off];
        __syncthreads();
    }
    if (t == 0) {
        g_rowsse[row] = sh[0];
        out[BD + 1 + row] = (float)code;
    }
}

// ---------------- final loss ----------------
__global__ void finalize_kernel(float* __restrict__ out) {
    __shared__ float sh[1024];
    int t = threadIdx.x;
    float s = 0.0f;
    for (int i = t; i < B_ROWS; i += 1024) s += g_rowsse[i];
    sh[t] = s;
    __syncthreads();
    #pragma unroll
    for (int off = 512; off > 0; off >>= 1) {
        if (t < off) sh[t] += sh[t + off];
        __syncthreads();
    }
    float sse = sh[0];
    __syncthreads();
    float e = 0.0f;
    for (int i = t; i < N_CODE; i += 1024) {
        float c = (float)g_counts[i];
        float p = c * (1.0f / (float)B_ROWS);
        e -= p * logf(p + 1e-10f);
    }
    sh[t] = e;
    __syncthreads();
    #pragma unroll
    for (int off = 512; off > 0; off >>= 1) {
        if (t < off) sh[t] += sh[t + off];
        __syncthreads();
    }
    if (t == 0) {
        float mse = sse / (float)BD;
        float entropy_loss = 1.0f - sh[0] / logf((float)N_CODE);
        out[BD] = 1.25f * mse + 0.1f * entropy_loss;
    }
}

// ---------------- launch ----------------
extern "C" void kernel_launch(void* const* d_in, const int* in_sizes, int n_in,
                              void* d_out, int out_size) {
    const float* z = (const float*)d_in[0];
    const float* W = (const float*)d_in[1];
    float* out = (float*)d_out;

    float* zz; cudaGetSymbolAddress((void**)&zz, g_zz);
    float* wn; cudaGetSymbolAddress((void**)&wn, g_wn);

    int nsm = 148;
    cudaDeviceGetAttribute(&nsm, cudaDevAttrMultiProcessorCount, 0);

    cudaFuncSetAttribute(vq_mma_kernel,
                         cudaFuncAttributeMaxDynamicSharedMemorySize, SMEM_TOTAL);

    pack_z_kernel<<<(B_ROWS * DIM + 255) / 256, 256>>>(z);
    pack_w_kernel<<<(N_CODE * DIM + 255) / 256, 256>>>(W);
    rownorm_kernel<<<B_ROWS / 8, 256>>>(z, zz, B_ROWS);
    rownorm_kernel<<<N_CODE / 8, 256>>>(W, wn, N_CODE);
    init_kernel<<<B_ROWS / 256, 256>>>();

    vq_mma_kernel<<<nsm, 256, SMEM_TOTAL>>>(nsm);

    hist_kernel<<<B_ROWS / 256, 256>>>();
    gather_sse_kernel<<<B_ROWS, 128>>>(z, W, out);
    finalize_kernel<<<1, 1024>>>(out);
}

// round 6
// speedup vs baseline: 5.9586x; 1.7229x over previous
#include <cuda_runtime.h>
#include <cuda_bf16.h>
#include <cstdint>
#include <math.h>

#define B_ROWS 32768
#define N_CODE 8192
#define DIM    512
#define BD     (B_ROWS * DIM)

#define UNITS  8192            // 256 mt x 32 nt, unit tile 128x256
#define NKC    8               // K-chunks of 64 (K=512, hi-only)
#define STAGES 3
#define STAGE_BYTES 49152      // A 16K (128x128B) + B 32K (256x128B)
#define SMEM_TOTAL (STAGES * STAGE_BYTES)

#define CAP    128
#define MARGIN 0.75f

// ---------------- device scratch ----------------
__device__ __nv_bfloat16 g_Az[(size_t)B_ROWS * DIM];   // 32 MB (hi only)
__device__ __nv_bfloat16 g_Bw[(size_t)N_CODE * DIM];   // 8 MB
__device__ float g_zz[B_ROWS];
__device__ float g_wn[N_CODE];
__device__ unsigned g_rmin[B_ROWS];        // ordered-float running min
__device__ int g_ccnt[B_ROWS];
__device__ int g_cand[(size_t)B_ROWS * CAP];   // 16 MB
__device__ int g_idx[B_ROWS];
__device__ int g_counts[N_CODE];
__device__ float g_rowsse[B_ROWS];

// ---------------- helpers ----------------
__device__ __forceinline__ uint32_t smem_u32(const void* p) {
    uint32_t a;
    asm("{ .reg .u64 t; cvta.to.shared.u64 t, %1; cvt.u32.u64 %0, t; }" : "=r"(a) : "l"(p));
    return a;
}
__device__ __forceinline__ void cp16(uint32_t dst, const void* src) {
    asm volatile("cp.async.cg.shared.global [%0], [%1], 16;" :: "r"(dst), "l"(src));
}
#define CP_COMMIT() asm volatile("cp.async.commit_group;" ::: "memory")
#define CP_WAIT1()  asm volatile("cp.async.wait_group 1;" ::: "memory")

#define LDM_X4(r0, r1, r2, r3, a)                                              \
    asm volatile("ldmatrix.sync.aligned.m8n8.x4.shared.b16 {%0,%1,%2,%3}, [%4];" \
        : "=r"(r0), "=r"(r1), "=r"(r2), "=r"(r3) : "r"(a))

#define MMA_BF16(d, a, b)                                                      \
    asm volatile("mma.sync.aligned.m16n8k16.row.col.f32.bf16.bf16.f32 "        \
        "{%0,%1,%2,%3},{%4,%5,%6,%7},{%8,%9},{%0,%1,%2,%3};"                   \
        : "+f"((d)[0]), "+f"((d)[1]), "+f"((d)[2]), "+f"((d)[3])               \
        : "r"((a)[0]), "r"((a)[1]), "r"((a)[2]), "r"((a)[3]),                  \
          "r"((b)[0]), "r"((b)[1]))

__device__ __forceinline__ uint32_t f2ord(float f) {
    uint32_t u = __float_as_uint(f);
    return (u & 0x80000000u) ? ~u : (u | 0x80000000u);
}
__device__ __forceinline__ float ord2f(uint32_t k) {
    return (k & 0x80000000u) ? __uint_as_float(k ^ 0x80000000u)
                             : __uint_as_float(~k);
}

// ---------------- pack: fp32 -> bf16 (hi only) ----------------
__global__ void pack_z_kernel(const float* __restrict__ z) {
    size_t i = (size_t)blockIdx.x * blockDim.x + threadIdx.x;
    if (i < (size_t)B_ROWS * DIM) g_Az[i] = __float2bfloat16(z[i]);
}
__global__ void pack_w_kernel(const float* __restrict__ W) {
    size_t i = (size_t)blockIdx.x * blockDim.x + threadIdx.x;
    if (i < (size_t)N_CODE * DIM) g_Bw[i] = __float2bfloat16(W[i]);
}

// ---------------- row norms ----------------
__global__ void rownorm_kernel(const float* __restrict__ x, float* __restrict__ out, int rows) {
    int warp = (blockIdx.x * blockDim.x + threadIdx.x) >> 5;
    int lane = threadIdx.x & 31;
    if (warp >= rows) return;
    const float4* p = (const float4*)(x + (size_t)warp * DIM);
    float s = 0.0f;
    #pragma unroll
    for (int i = lane; i < DIM / 4; i += 32) {
        float4 v = p[i];
        s = fmaf(v.x, v.x, s); s = fmaf(v.y, v.y, s);
        s = fmaf(v.z, v.z, s); s = fmaf(v.w, v.w, s);
    }
    #pragma unroll
    for (int off = 16; off > 0; off >>= 1) s += __shfl_down_sync(0xFFFFFFFFu, s, off);
    if (lane == 0) out[warp] = s;
}

__global__ void init_kernel() {
    int i = blockIdx.x * blockDim.x + threadIdx.x;
    if (i < N_CODE) g_counts[i] = 0;
    if (i < B_ROWS) { g_rmin[i] = 0xFFFFFFFFu; g_ccnt[i] = 0; }
}

// ---------------- pass 1: hi-only HMMA screen + candidate collection ------
// persistent grid; unit tile 128x256, K=512. 8 warps: warpM=wid&1, warpN=wid>>1.
__global__ __launch_bounds__(256, 1) void vq_screen_kernel(int grid) {
    extern __shared__ char smem[];
    const uint32_t sb = smem_u32(smem);

    const int tid   = threadIdx.x;
    const int lane  = tid & 31;
    const int wid   = tid >> 5;
    const int warpM = wid & 1;
    const int warpN = wid >> 1;
    const int q     = lane & 3;
    const int bid   = blockIdx.x;

    const int nu = (UNITS - 1 - bid) / grid + 1;
    const int GT = nu * NKC;

    float acc[4][8][4];
    #pragma unroll
    for (int mi = 0; mi < 4; mi++)
        #pragma unroll
        for (int n8 = 0; n8 < 8; n8++)
            #pragma unroll
            for (int r = 0; r < 4; r++) acc[mi][n8][r] = 0.0f;

    auto load_tiles = [&](int g) {
        const int ui = g >> 3;
        const int kc = g & 7;
        const int w  = bid + ui * grid;
        const int mt = w >> 5;
        const int nt = w & 31;
        const uint32_t stage = sb + (uint32_t)(g % STAGES) * STAGE_BYTES;
        const __nv_bfloat16* Asrc = g_Az + (size_t)(mt * 128) * DIM + kc * 64;
        const __nv_bfloat16* Bsrc = g_Bw + (size_t)(nt * 256) * DIM + kc * 64;
        #pragma unroll
        for (int i = 0; i < 4; i++) {
            int lin = tid + 256 * i;
            int row = lin >> 3, c = lin & 7;
            uint32_t off = (uint32_t)row * 128u + (uint32_t)((c ^ (row & 7)) << 4);
            cp16(stage + off, Asrc + (size_t)row * DIM + c * 8);
        }
        #pragma unroll
        for (int i = 0; i < 8; i++) {
            int lin = tid + 256 * i;
            int row = lin >> 3, c = lin & 7;
            uint32_t off = (uint32_t)row * 128u + (uint32_t)((c ^ (row & 7)) << 4);
            cp16(stage + 16384u + off, Bsrc + (size_t)row * DIM + c * 8);
        }
        CP_COMMIT();
    };

    load_tiles(0);
    if (GT > 1) load_tiles(1);

    for (int g = 0; g < GT; g++) {
        CP_WAIT1();
        __syncthreads();
        if (g + 2 < GT) load_tiles(g + 2);

        const uint32_t Abase = sb + (uint32_t)(g % STAGES) * STAGE_BYTES;
        const uint32_t Bbase = Abase + 16384u;

        #pragma unroll
        for (int s = 0; s < 4; s++) {
            uint32_t afr[4][4];
            #pragma unroll
            for (int mi = 0; mi < 4; mi++) {
                int row = warpM * 64 + mi * 16 + (lane & 15);
                int c = 2 * s + (lane >> 4);
                uint32_t addr = Abase + (uint32_t)row * 128u + (uint32_t)((c ^ (row & 7)) << 4);
                LDM_X4(afr[mi][0], afr[mi][1], afr[mi][2], afr[mi][3], addr);
            }
            uint32_t bfr[8][2];
            #pragma unroll
            for (int ni2 = 0; ni2 < 4; ni2++) {
                int row = warpN * 64 + ni2 * 16 + ((lane >> 4) << 3) + (lane & 7);
                int c = 2 * s + ((lane >> 3) & 1);
                uint32_t addr = Bbase + (uint32_t)row * 128u + (uint32_t)((c ^ (row & 7)) << 4);
                LDM_X4(bfr[2 * ni2][0], bfr[2 * ni2][1],
                       bfr[2 * ni2 + 1][0], bfr[2 * ni2 + 1][1], addr);
            }
            #pragma unroll
            for (int mi = 0; mi < 4; mi++)
                #pragma unroll
                for (int n8 = 0; n8 < 8; n8++)
                    MMA_BF16(acc[mi][n8], afr[mi], bfr[n8]);
        }

        if ((g & 7) == 7) {
            // ---------- epilogue: per-warp threshold + candidate append ----------
            const int ui = g >> 3;
            const int w  = bid + ui * grid;
            const int mt = w >> 5;
            const int nt = w & 31;
            const int cb = nt * 256 + warpN * 64 + 2 * q;

            float wnv[16];
            #pragma unroll
            for (int n8 = 0; n8 < 8; n8++) {
                wnv[n8 * 2]     = __ldg(&g_wn[cb + n8 * 8]);
                wnv[n8 * 2 + 1] = __ldg(&g_wn[cb + n8 * 8 + 1]);
            }

            #pragma unroll
            for (int mi = 0; mi < 4; mi++) {
                #pragma unroll
                for (int h = 0; h < 2; h++) {
                    const int row = mt * 128 + warpM * 64 + mi * 16 + (lane >> 2) + 8 * h;
                    const float zzv = __ldg(&g_zz[row]);
                    float d16[16];
                    float bv = __int_as_float(0x7f800000);
                    #pragma unroll
                    for (int n8 = 0; n8 < 8; n8++) {
                        #pragma unroll
                        for (int j = 0; j < 2; j++) {
                            float d = (zzv + wnv[n8 * 2 + j]) - 2.0f * acc[mi][n8][h * 2 + j];
                            d16[n8 * 2 + j] = d;
                            bv = fminf(bv, d);
                        }
                    }
                    // min over the 4-lane q group
                    #pragma unroll
                    for (int off = 1; off <= 2; off <<= 1)
                        bv = fminf(bv, __shfl_xor_sync(0xFFFFFFFFu, bv, off));
                    // q==0 updates global running min, computes threshold
                    uint32_t thr_bits = 0;
                    if (q == 0) {
                        uint32_t key = f2ord(bv);
                        uint32_t old = atomicMin(&g_rmin[row], key);
                        thr_bits = (key < old) ? key : old;
                    }
                    thr_bits = __shfl_sync(0xFFFFFFFFu, thr_bits, lane & ~3);
                    const float thr = ord2f(thr_bits) + MARGIN;
                    #pragma unroll
                    for (int k = 0; k < 16; k++) {
                        if (d16[k] < thr) {
                            int pos = atomicAdd(&g_ccnt[row], 1);
                            if (pos < CAP)
                                g_cand[(size_t)row * CAP + pos] = cb + (k >> 1) * 8 + (k & 1);
                        }
                    }
                }
            }
            #pragma unroll
            for (int mi = 0; mi < 4; mi++)
                #pragma unroll
                for (int n8 = 0; n8 < 8; n8++)
                    #pragma unroll
                    for (int r = 0; r < 4; r++) acc[mi][n8][r] = 0.0f;
        }
    }
}

// ---------------- pass 2: exact fp32 rescore of candidates ----------------
// one warp per row; lexicographic (d, code) min = first-occurrence argmin.
__global__ __launch_bounds__(256, 4) void rescore_kernel(const float* __restrict__ z,
                                                         const float* __restrict__ W) {
    const int lane = threadIdx.x & 31;
    const int row = blockIdx.x * 8 + (threadIdx.x >> 5);

    // this lane's 16 z values
    float zr[16];
    const float4* zp = (const float4*)(z + (size_t)row * DIM + lane * 16);
    #pragma unroll
    for (int i = 0; i < 4; i++) {
        float4 v = zp[i];
        zr[i * 4] = v.x; zr[i * 4 + 1] = v.y; zr[i * 4 + 2] = v.z; zr[i * 4 + 3] = v.w;
    }
    const float zzv = g_zz[row];
    const int cnt = g_ccnt[row];

    float bv = __int_as_float(0x7f800000);
    int bc = 0x7FFFFFFF;

    const int n = (cnt <= CAP) ? cnt : N_CODE;   // fallback: full scan (never in practice)
    for (int i = 0; i < n; i++) {
        const int code = (cnt <= CAP) ? g_cand[(size_t)row * CAP + i] : i;
        const float4* wp = (const float4*)(W + (size_t)code * DIM + lane * 16);
        float s = 0.0f;
        #pragma unroll
        for (int k = 0; k < 4; k++) {
            float4 v = wp[k];
            s = fmaf(zr[k * 4], v.x, s);
            s = fmaf(zr[k * 4 + 1], v.y, s);
            s = fmaf(zr[k * 4 + 2], v.z, s);
            s = fmaf(zr[k * 4 + 3], v.w, s);
        }
        #pragma unroll
        for (int off = 16; off > 0; off >>= 1) s += __shfl_xor_sync(0xFFFFFFFFu, s, off);
        const float d = (zzv + g_wn[code]) - 2.0f * s;
        if (d < bv || (d == bv && code < bc)) { bv = d; bc = code; }
    }
    if (lane == 0) g_idx[row] = bc;
}

// ---------------- histogram ----------------
__global__ void hist_kernel() {
    int i = blockIdx.x * blockDim.x + threadIdx.x;
    if (i < B_ROWS) atomicAdd(&g_counts[g_idx[i]], 1);
}

// ---------------- gather + per-row SSE + index write ----------------
__global__ void gather_sse_kernel(const float* __restrict__ z,
                                  const float* __restrict__ W,
                                  float* __restrict__ out) {
    __shared__ float sh[128];
    int row = blockIdx.x;
    int t = threadIdx.x;
    int code = g_idx[row];
    const float4* zp = (const float4*)(z + (size_t)row * DIM);
    const float4* wp = (const float4*)(W + (size_t)code * DIM);
    float4 a = zp[t];
    float4 b = wp[t];
    ((float4*)out)[(size_t)row * (DIM / 4) + t] = b;
    float dx = a.x - b.x, dy = a.y - b.y, dz = a.z - b.z, dw = a.w - b.w;
    sh[t] = dx * dx + dy * dy + dz * dz + dw * dw;
    __syncthreads();
    #pragma unroll
    for (int off = 64; off > 0; off >>= 1) {
        if (t < off) sh[t] += sh[t + off];
        __syncthreads();
    }
    if (t == 0) {
        g_rowsse[row] = sh[0];
        out[BD + 1 + row] = (float)code;
    }
}

// ---------------- final loss ----------------
__global__ void finalize_kernel(float* __restrict__ out) {
    __shared__ float sh[1024];
    int t = threadIdx.x;
    float s = 0.0f;
    for (int i = t; i < B_ROWS; i += 1024) s += g_rowsse[i];
    sh[t] = s;
    __syncthreads();
    #pragma unroll
    for (int off = 512; off > 0; off >>= 1) {
        if (t < off) sh[t] += sh[t + off];
        __syncthreads();
    }
    float sse = sh[0];
    __syncthreads();
    float e = 0.0f;
    for (int i = t; i < N_CODE; i += 1024) {
        float c = (float)g_counts[i];
        float p = c * (1.0f / (float)B_ROWS);
        e -= p * logf(p + 1e-10f);
    }
    sh[t] = e;
    __syncthreads();
    #pragma unroll
    for (int off = 512; off > 0; off >>= 1) {
        if (t < off) sh[t] += sh[t + off];
        __syncthreads();
    }
    if (t == 0) {
        float mse = sse / (float)BD;
        float entropy_loss = 1.0f - sh[0] / logf((float)N_CODE);
        out[BD] = 1.25f * mse + 0.1f * entropy_loss;
    }
}

// ---------------- launch ----------------
extern "C" void kernel_launch(void* const* d_in, const int* in_sizes, int n_in,
                              void* d_out, int out_size) {
    const float* z = (const float*)d_in[0];
    const float* W = (const float*)d_in[1];
    float* out = (float*)d_out;

    float* zz; cudaGetSymbolAddress((void**)&zz, g_zz);
    float* wn; cudaGetSymbolAddress((void**)&wn, g_wn);

    int nsm = 148;
    cudaDeviceGetAttribute(&nsm, cudaDevAttrMultiProcessorCount, 0);

    cudaFuncSetAttribute(vq_screen_kernel,
                         cudaFuncAttributeMaxDynamicSharedMemorySize, SMEM_TOTAL);

    pack_z_kernel<<<(B_ROWS * DIM + 255) / 256, 256>>>(z);
    pack_w_kernel<<<(N_CODE * DIM + 255) / 256, 256>>>(W);
    rownorm_kernel<<<B_ROWS / 8, 256>>>(z, zz, B_ROWS);
    rownorm_kernel<<<N_CODE / 8, 256>>>(W, wn, N_CODE);
    init_kernel<<<B_ROWS / 256, 256>>>();

    vq_screen_kernel<<<nsm, 256, SMEM_TOTAL>>>(nsm);

    rescore_kernel<<<B_ROWS / 8, 256>>>(z, W);
    hist_kernel<<<B_ROWS / 256, 256>>>();
    gather_sse_kernel<<<B_ROWS, 128>>>(z, W, out);
    finalize_kernel<<<1, 1024>>>(out);
}